// round 4
// baseline (speedup 1.0000x reference)
#include <cuda_runtime.h>
#include <cuda_bf16.h>

#define N_NODES 100000
#define N_EDGES 1600000
#define IN_DIM  512
#define OUT_DIM 32
#define KSTEPS  10
#define ALPHA   0.1f

// ---------------- device scratch (allocation-free) ----------------
__device__ float  g_h[N_NODES * OUT_DIM];      // 12.8 MB
__device__ float  g_z[N_NODES * OUT_DIM];      // 12.8 MB ping buffer
__device__ int    g_src[N_EDGES];
__device__ int    g_dst[N_EDGES];
__device__ int    g_deg[N_NODES];
__device__ float  g_dinv[N_NODES];
__device__ int    g_rowptr[N_NODES + 1];
__device__ int    g_cursor[N_NODES];
__device__ float2 g_packed[N_EDGES];           // {src as int-bits, dinv[src]}
__device__ int    g_partial[128];
__device__ int    g_is64;

// ---------------- dtype sniff: int64 edges have zero high words ----------------
__global__ void k_detect(const int* __restrict__ e32) {
    int ok = 1;
#pragma unroll
    for (int i = 1; i < 64; i += 2)
        if (e32[i] != 0) ok = 0;
    g_is64 = ok;
}

// ---------------- degree init (self-loop counted) ----------------
__global__ void k_init_deg() {
    int i = blockIdx.x * blockDim.x + threadIdx.x;
    if (i < N_NODES) g_deg[i] = 1;   // self loop
}

// ---------------- decode edges + count in-degrees (fused) ----------------
__global__ void k_decode_count(const void* __restrict__ ei) {
    int e = blockIdx.x * blockDim.x + threadIdx.x;
    if (e >= N_EDGES) return;
    int s, d;
    if (g_is64) {
        const long long* p = (const long long*)ei;
        s = (int)p[e];
        d = (int)p[N_EDGES + e];
    } else {
        const int* p = (const int*)ei;
        s = p[e];
        d = p[N_EDGES + e];
    }
    if (s < 0) s = 0; if (s >= N_NODES) s = N_NODES - 1;
    if (d < 0) d = 0; if (d >= N_NODES) d = N_NODES - 1;
    g_src[e] = s;
    g_dst[e] = d;
    atomicAdd(&g_deg[d], 1);
}

// ---------------- dinv = rsqrt(deg) ----------------
__global__ void k_dinv() {
    int i = blockIdx.x * blockDim.x + threadIdx.x;
    if (i < N_NODES) g_dinv[i] = rsqrtf((float)g_deg[i]);
}

// ---------------- scan kernel 1: per-block sums of (deg-1) ----------------
__global__ void k_blocksum() {
    int base = blockIdx.x * 1024;
    int t = threadIdx.x;
    int s = 0;
#pragma unroll
    for (int i = 0; i < 4; i++) {
        int idx = base + t * 4 + i;
        if (idx < N_NODES) s += g_deg[idx] - 1;
    }
#pragma unroll
    for (int o = 16; o; o >>= 1) s += __shfl_down_sync(0xffffffffu, s, o);
    __shared__ int ws[8];
    if ((t & 31) == 0) ws[t >> 5] = s;
    __syncthreads();
    if (t == 0) {
        int tot = 0;
#pragma unroll
        for (int i = 0; i < 8; i++) tot += ws[i];
        g_partial[blockIdx.x] = tot;
    }
}

// ---------------- scan kernel 2: exclusive scan of block sums (1 warp) ----------------
__global__ void k_scanpartial(int nb) {
    int lane = threadIdx.x;
    int v[4];
    int tsum = 0;
#pragma unroll
    for (int i = 0; i < 4; i++) {
        int idx = lane * 4 + i;
        v[i] = (idx < nb) ? g_partial[idx] : 0;
        tsum += v[i];
    }
    int inc = tsum;
#pragma unroll
    for (int o = 1; o < 32; o <<= 1) {
        int y = __shfl_up_sync(0xffffffffu, inc, o);
        if (lane >= o) inc += y;
    }
    int run = inc - tsum;   // exclusive
#pragma unroll
    for (int i = 0; i < 4; i++) {
        int idx = lane * 4 + i;
        if (idx < nb) { g_partial[idx] = run; run += v[i]; }
    }
    int total = __shfl_sync(0xffffffffu, inc, 31);
    if (lane == 0) g_rowptr[N_NODES] = total;
}

// ---------------- scan kernel 3: full exclusive scan -> rowptr & cursor ----------------
__global__ void k_blockscan() {
    int t = threadIdx.x;
    int base = blockIdx.x * 1024 + t * 4;
    int v[4];
    int tsum = 0;
#pragma unroll
    for (int i = 0; i < 4; i++) {
        int idx = base + i;
        v[i] = (idx < N_NODES) ? (g_deg[idx] - 1) : 0;
        tsum += v[i];
    }
    int lane = t & 31, warp = t >> 5;
    int inc = tsum;
#pragma unroll
    for (int o = 1; o < 32; o <<= 1) {
        int y = __shfl_up_sync(0xffffffffu, inc, o);
        if (lane >= o) inc += y;
    }
    int excl = inc - tsum;
    __shared__ int wtot[8];
    if (lane == 31) wtot[warp] = inc;
    __syncthreads();
    if (t == 0) {
        int acc = 0;
#pragma unroll
        for (int i = 0; i < 8; i++) { int x = wtot[i]; wtot[i] = acc; acc += x; }
    }
    __syncthreads();
    int off = g_partial[blockIdx.x] + wtot[warp] + excl;
#pragma unroll
    for (int i = 0; i < 4; i++) {
        int idx = base + i;
        if (idx < N_NODES) { g_rowptr[idx] = off; g_cursor[idx] = off; off += v[i]; }
    }
}

// ---------------- CSR scatter ----------------
__global__ void k_scatter() {
    int e = blockIdx.x * blockDim.x + threadIdx.x;
    if (e >= N_EDGES) return;
    int s = g_src[e];
    int d = g_dst[e];
    int pos = atomicAdd(&g_cursor[d], 1);
    g_packed[pos] = make_float2(__int_as_float(s), g_dinv[s]);
}

// ---------------- dense projection: h = x @ W^T + b ----------------
// 256 threads per block compute a 128-row x 32-col tile.
// Per 32-wide k-chunk: x staged transposed (xT[kk][row]) for LDS.128 row-quads,
// W staged duplicated (Wd[kk][2j]=Wd[kk][2j+1]) so w broadcast-pairs come free.
// Each thread: 4 rows x 4 cols via 8 fma.rn.f32x2 per k. No shuffles.
__global__ __launch_bounds__(256) void k_gemm(const float* __restrict__ x,
                                              const float* __restrict__ W,
                                              const float* __restrict__ b) {
    __shared__ float xT[32][132];   // [kk][row], stride 132 keeps LDS.128 alignment
    __shared__ float Wd[32][64];    // [kk][2j(+1)] duplicated pairs

    int t  = threadIdx.x;
    int tr = t >> 3;                // 0..31 -> rows 4*tr .. 4*tr+3
    int tc = t & 7;                 // 0..7  -> cols 4*tc .. 4*tc+3
    int row0 = blockIdx.x * 128;

    unsigned long long acc[2][4];
#pragma unroll
    for (int p = 0; p < 2; p++)
#pragma unroll
        for (int j = 0; j < 4; j++) acc[p][j] = 0ull;

    for (int chunk = 0; chunk < 16; chunk++) {
        int k0 = chunk * 32;
        __syncthreads();
        // stage W chunk (duplicated pairs)
        {
            int j  = t >> 3;        // output col 0..31
            int c4 = t & 7;
            float4 wv = *(const float4*)&W[j * IN_DIM + k0 + c4 * 4];
            float wa[4] = {wv.x, wv.y, wv.z, wv.w};
#pragma unroll
            for (int i = 0; i < 4; i++) {
                Wd[c4 * 4 + i][2 * j]     = wa[i];
                Wd[c4 * 4 + i][2 * j + 1] = wa[i];
            }
        }
        // stage x chunk transposed
#pragma unroll
        for (int jj = 0; jj < 4; jj++) {
            int idx = t + jj * 256;
            int row = idx >> 3;     // 0..127
            int c4  = idx & 7;
            int gr  = row0 + row;
            if (gr >= N_NODES) gr = N_NODES - 1;   // clamp (store is guarded)
            float4 xv = *(const float4*)&x[(size_t)gr * IN_DIM + k0 + c4 * 4];
            float xa[4] = {xv.x, xv.y, xv.z, xv.w};
#pragma unroll
            for (int i = 0; i < 4; i++)
                xT[c4 * 4 + i][row] = xa[i];
        }
        __syncthreads();
#pragma unroll
        for (int kk = 0; kk < 32; kk++) {
            float4 xv  = *(const float4*)&xT[kk][4 * tr];
            float4 wv0 = *(const float4*)&Wd[kk][8 * tc];
            float4 wv1 = *(const float4*)&Wd[kk][8 * tc + 4];
            unsigned long long xp0, xp1, wp0, wp1, wp2, wp3;
            asm("mov.b64 %0, {%1, %2};" : "=l"(xp0) : "f"(xv.x),  "f"(xv.y));
            asm("mov.b64 %0, {%1, %2};" : "=l"(xp1) : "f"(xv.z),  "f"(xv.w));
            asm("mov.b64 %0, {%1, %2};" : "=l"(wp0) : "f"(wv0.x), "f"(wv0.y));
            asm("mov.b64 %0, {%1, %2};" : "=l"(wp1) : "f"(wv0.z), "f"(wv0.w));
            asm("mov.b64 %0, {%1, %2};" : "=l"(wp2) : "f"(wv1.x), "f"(wv1.y));
            asm("mov.b64 %0, {%1, %2};" : "=l"(wp3) : "f"(wv1.z), "f"(wv1.w));
            asm("fma.rn.f32x2 %0, %1, %2, %0;" : "+l"(acc[0][0]) : "l"(xp0), "l"(wp0));
            asm("fma.rn.f32x2 %0, %1, %2, %0;" : "+l"(acc[0][1]) : "l"(xp0), "l"(wp1));
            asm("fma.rn.f32x2 %0, %1, %2, %0;" : "+l"(acc[0][2]) : "l"(xp0), "l"(wp2));
            asm("fma.rn.f32x2 %0, %1, %2, %0;" : "+l"(acc[0][3]) : "l"(xp0), "l"(wp3));
            asm("fma.rn.f32x2 %0, %1, %2, %0;" : "+l"(acc[1][0]) : "l"(xp1), "l"(wp0));
            asm("fma.rn.f32x2 %0, %1, %2, %0;" : "+l"(acc[1][1]) : "l"(xp1), "l"(wp1));
            asm("fma.rn.f32x2 %0, %1, %2, %0;" : "+l"(acc[1][2]) : "l"(xp1), "l"(wp2));
            asm("fma.rn.f32x2 %0, %1, %2, %0;" : "+l"(acc[1][3]) : "l"(xp1), "l"(wp3));
        }
    }

    float bj0 = b[4 * tc], bj1 = b[4 * tc + 1], bj2 = b[4 * tc + 2], bj3 = b[4 * tc + 3];
#pragma unroll
    for (int i = 0; i < 4; i++) {
        int r = row0 + 4 * tr + i;
        if (r < N_NODES) {
            int p = i >> 1;
            float v[4];
#pragma unroll
            for (int j = 0; j < 4; j++) {
                float lo, hi;
                asm("mov.b64 {%0, %1}, %2;" : "=f"(lo), "=f"(hi) : "l"(acc[p][j]));
                v[j] = (i & 1) ? hi : lo;
            }
            *(float4*)&g_h[(size_t)r * 32 + 4 * tc] =
                make_float4(v[0] + bj0, v[1] + bj1, v[2] + bj2, v[3] + bj3);
        }
    }
}

// ---------------- propagation step (pull, warp per node, lane = out dim) ----------------
// 8 independent gathers in flight per batch.
__global__ __launch_bounds__(256) void k_prop(int srcSel, int dstSel, float* __restrict__ dout) {
    int gw   = (blockIdx.x * blockDim.x + threadIdx.x) >> 5;
    int lane = threadIdx.x & 31;
    const float* zin = (srcSel == 0) ? g_h : (srcSel == 1) ? g_z : dout;
    float* zout = (dstSel == 1) ? g_z : dout;

    int start = g_rowptr[gw];
    int end   = g_rowptr[gw + 1];

    float acc0 = 0.f, acc1 = 0.f, acc2 = 0.f, acc3 = 0.f;
    for (int base = start; base < end; base += 32) {
        int m = end - base;
        if (m > 32) m = 32;
        float2 p = make_float2(0.f, 0.f);
        if (lane < m) p = g_packed[base + lane];
        int   si = __float_as_int(p.x);
        float wi = p.y;
        int kk = 0;
        for (; kk + 8 <= m; kk += 8) {
            int s[8]; float w[8], z[8];
#pragma unroll
            for (int q = 0; q < 8; q++) {
                s[q] = __shfl_sync(0xffffffffu, si, kk + q);
                w[q] = __shfl_sync(0xffffffffu, wi, kk + q);
            }
#pragma unroll
            for (int q = 0; q < 8; q++)
                z[q] = zin[s[q] * 32 + lane];
            acc0 = fmaf(w[0], z[0], acc0);
            acc1 = fmaf(w[1], z[1], acc1);
            acc2 = fmaf(w[2], z[2], acc2);
            acc3 = fmaf(w[3], z[3], acc3);
            acc0 = fmaf(w[4], z[4], acc0);
            acc1 = fmaf(w[5], z[5], acc1);
            acc2 = fmaf(w[6], z[6], acc2);
            acc3 = fmaf(w[7], z[7], acc3);
        }
        for (; kk < m; kk++) {
            int   s = __shfl_sync(0xffffffffu, si, kk);
            float w = __shfl_sync(0xffffffffu, wi, kk);
            acc0 = fmaf(w, zin[s * 32 + lane], acc0);
        }
    }
    float di = g_dinv[gw];
    float zi = zin[gw * 32 + lane];
    float agg = di * fmaf(di, zi, (acc0 + acc1) + (acc2 + acc3));
    zout[gw * 32 + lane] = (1.0f - ALPHA) * agg + ALPHA * g_h[gw * 32 + lane];
}

// ---------------- host launcher ----------------
extern "C" void kernel_launch(void* const* d_in, const int* in_sizes, int n_in,
                              void* d_out, int out_size) {
    const float* x  = (const float*)d_in[0];
    const float* W  = (const float*)d_in[1];
    const float* b  = (const float*)d_in[2];
    const void*  ei = d_in[3];
    float* out = (float*)d_out;

    const int NB = (N_NODES + 1023) / 1024;   // 98

    k_detect<<<1, 1>>>((const int*)ei);
    k_init_deg<<<(N_NODES + 255) / 256, 256>>>();
    k_decode_count<<<(N_EDGES + 255) / 256, 256>>>(ei);
    k_dinv<<<(N_NODES + 255) / 256, 256>>>();
    k_blocksum<<<NB, 256>>>();
    k_scanpartial<<<1, 32>>>(NB);
    k_blockscan<<<NB, 256>>>();
    k_scatter<<<N_EDGES / 256, 256>>>();
    k_gemm<<<(N_NODES + 127) / 128, 256>>>(x, W, b);

    // step 1 reads h, writes g_z; even steps write dout; odd steps (>=3) write g_z.
    k_prop<<<N_NODES * 32 / 256, 256>>>(0, 1, out);
    for (int s = 2; s <= KSTEPS; s++) {
        if ((s & 1) == 0) k_prop<<<N_NODES * 32 / 256, 256>>>(1, 2, out);
        else              k_prop<<<N_NODES * 32 / 256, 256>>>(2, 1, out);
    }
}

// round 5
// speedup vs baseline: 1.2908x; 1.2908x over previous
#include <cuda_runtime.h>
#include <cuda_bf16.h>

#define N_NODES 100000
#define N_EDGES 1600000
#define IN_DIM  512
#define OUT_DIM 32
#define KSTEPS  10
#define ALPHA   0.1f

typedef unsigned long long ull;

// ---------------- device scratch (allocation-free) ----------------
__device__ float  g_h[N_NODES * OUT_DIM];      // 12.8 MB
__device__ float  g_z[N_NODES * OUT_DIM];      // 12.8 MB ping buffer
__device__ int    g_src[N_EDGES];
__device__ int    g_dst[N_EDGES];
__device__ int    g_deg[N_NODES];
__device__ float  g_dinv[N_NODES];
__device__ int    g_rowptr[N_NODES + 1];
__device__ int    g_cursor[N_NODES];
__device__ float2 g_packed[N_EDGES];           // {src as int-bits, dinv[src]}
__device__ int    g_partial[128];
__device__ int    g_is64;

// ---------------- dtype sniff: int64 edges have zero high words ----------------
__global__ void k_detect(const int* __restrict__ e32) {
    int ok = 1;
#pragma unroll
    for (int i = 1; i < 64; i += 2)
        if (e32[i] != 0) ok = 0;
    g_is64 = ok;
}

// ---------------- degree init (self-loop counted) ----------------
__global__ void k_init_deg() {
    int i = blockIdx.x * blockDim.x + threadIdx.x;
    if (i < N_NODES) g_deg[i] = 1;   // self loop
}

// ---------------- decode edges + count in-degrees (fused) ----------------
__global__ void k_decode_count(const void* __restrict__ ei) {
    int e = blockIdx.x * blockDim.x + threadIdx.x;
    if (e >= N_EDGES) return;
    int s, d;
    if (g_is64) {
        const long long* p = (const long long*)ei;
        s = (int)p[e];
        d = (int)p[N_EDGES + e];
    } else {
        const int* p = (const int*)ei;
        s = p[e];
        d = p[N_EDGES + e];
    }
    if (s < 0) s = 0; if (s >= N_NODES) s = N_NODES - 1;
    if (d < 0) d = 0; if (d >= N_NODES) d = N_NODES - 1;
    g_src[e] = s;
    g_dst[e] = d;
    atomicAdd(&g_deg[d], 1);
}

// ---------------- dinv = rsqrt(deg) ----------------
__global__ void k_dinv() {
    int i = blockIdx.x * blockDim.x + threadIdx.x;
    if (i < N_NODES) g_dinv[i] = rsqrtf((float)g_deg[i]);
}

// ---------------- scan kernel 1: per-block sums of (deg-1) ----------------
__global__ void k_blocksum() {
    int base = blockIdx.x * 1024;
    int t = threadIdx.x;
    int s = 0;
#pragma unroll
    for (int i = 0; i < 4; i++) {
        int idx = base + t * 4 + i;
        if (idx < N_NODES) s += g_deg[idx] - 1;
    }
#pragma unroll
    for (int o = 16; o; o >>= 1) s += __shfl_down_sync(0xffffffffu, s, o);
    __shared__ int ws[8];
    if ((t & 31) == 0) ws[t >> 5] = s;
    __syncthreads();
    if (t == 0) {
        int tot = 0;
#pragma unroll
        for (int i = 0; i < 8; i++) tot += ws[i];
        g_partial[blockIdx.x] = tot;
    }
}

// ---------------- scan kernel 2: exclusive scan of block sums (1 warp) ----------------
__global__ void k_scanpartial(int nb) {
    int lane = threadIdx.x;
    int v[4];
    int tsum = 0;
#pragma unroll
    for (int i = 0; i < 4; i++) {
        int idx = lane * 4 + i;
        v[i] = (idx < nb) ? g_partial[idx] : 0;
        tsum += v[i];
    }
    int inc = tsum;
#pragma unroll
    for (int o = 1; o < 32; o <<= 1) {
        int y = __shfl_up_sync(0xffffffffu, inc, o);
        if (lane >= o) inc += y;
    }
    int run = inc - tsum;   // exclusive
#pragma unroll
    for (int i = 0; i < 4; i++) {
        int idx = lane * 4 + i;
        if (idx < nb) { g_partial[idx] = run; run += v[i]; }
    }
    int total = __shfl_sync(0xffffffffu, inc, 31);
    if (lane == 0) g_rowptr[N_NODES] = total;
}

// ---------------- scan kernel 3: full exclusive scan -> rowptr & cursor ----------------
__global__ void k_blockscan() {
    int t = threadIdx.x;
    int base = blockIdx.x * 1024 + t * 4;
    int v[4];
    int tsum = 0;
#pragma unroll
    for (int i = 0; i < 4; i++) {
        int idx = base + i;
        v[i] = (idx < N_NODES) ? (g_deg[idx] - 1) : 0;
        tsum += v[i];
    }
    int lane = t & 31, warp = t >> 5;
    int inc = tsum;
#pragma unroll
    for (int o = 1; o < 32; o <<= 1) {
        int y = __shfl_up_sync(0xffffffffu, inc, o);
        if (lane >= o) inc += y;
    }
    int excl = inc - tsum;
    __shared__ int wtot[8];
    if (lane == 31) wtot[warp] = inc;
    __syncthreads();
    if (t == 0) {
        int acc = 0;
#pragma unroll
        for (int i = 0; i < 8; i++) { int x = wtot[i]; wtot[i] = acc; acc += x; }
    }
    __syncthreads();
    int off = g_partial[blockIdx.x] + wtot[warp] + excl;
#pragma unroll
    for (int i = 0; i < 4; i++) {
        int idx = base + i;
        if (idx < N_NODES) { g_rowptr[idx] = off; g_cursor[idx] = off; off += v[i]; }
    }
}

// ---------------- CSR scatter ----------------
__global__ void k_scatter() {
    int e = blockIdx.x * blockDim.x + threadIdx.x;
    if (e >= N_EDGES) return;
    int s = g_src[e];
    int d = g_dst[e];
    int pos = atomicAdd(&g_cursor[d], 1);
    g_packed[pos] = make_float2(__int_as_float(s), g_dinv[s]);
}

// ---------------- dense projection: h = x @ W^T + b ----------------
// 256 threads (8 warps). Block tile: 64 rows x 32 cols. Warp w owns rows
// 8w..8w+7 (4 row-pairs), lane = output col. k chunked by 64.
// All 64-bit FFMA2 operands come straight from LDS.64 (no packing movs):
//   xPf[kk*66 + row]        : x transposed; a row-pair is 8 contiguous bytes
//                             -> warp-uniform broadcast LDS.64
//   Wdf[kk*66 + 2j, 2j+1]   : W duplicated -> per-lane LDS.64, conflict-free
// Inner loop per kk: 1 LDS.64 (w) + 4 broadcast LDS.64 (x) + 4 FFMA2.
__global__ __launch_bounds__(256) void k_gemm(const float* __restrict__ x,
                                              const float* __restrict__ W,
                                              const float* __restrict__ b) {
    __shared__ alignas(16) float xPf[64 * 66];   // 16.9 KB
    __shared__ alignas(16) float Wdf[64 * 66];   // 16.9 KB

    int t    = threadIdx.x;
    int lane = t & 31;
    int warp = t >> 5;
    int row0 = blockIdx.x * 64;

    ull acc0 = 0ull, acc1 = 0ull, acc2 = 0ull, acc3 = 0ull;

    for (int chunk = 0; chunk < 8; chunk++) {
        int k0 = chunk * 64;
        __syncthreads();
        // stage W chunk duplicated: Wdf[kk*66 + 2j (+1)] = W[j][k0+kk]
#pragma unroll
        for (int it = 0; it < 8; it++) {
            int gidx = t + it * 256;        // 0..2047
            int j  = gidx >> 6;             // 0..31
            int kk = gidx & 63;             // 0..63
            float wv = W[j * IN_DIM + k0 + kk];
            Wdf[kk * 66 + 2 * j]     = wv;
            Wdf[kk * 66 + 2 * j + 1] = wv;
        }
        // stage x chunk transposed: xPf[kk*66 + row] = x[row0+row][k0+kk]
#pragma unroll
        for (int it = 0; it < 4; it++) {
            int gidx = t + it * 256;        // 0..1023
            int row = gidx & 63;
            int q   = gidx >> 6;            // 0..15
            int gr  = row0 + row;
            if (gr >= N_NODES) gr = N_NODES - 1;
            float4 xv = *(const float4*)&x[(size_t)gr * IN_DIM + k0 + q * 4];
            xPf[(q * 4 + 0) * 66 + row] = xv.x;
            xPf[(q * 4 + 1) * 66 + row] = xv.y;
            xPf[(q * 4 + 2) * 66 + row] = xv.z;
            xPf[(q * 4 + 3) * 66 + row] = xv.w;
        }
        __syncthreads();

        const float* xb = &xPf[warp * 8];
        const float* wb = &Wdf[2 * lane];
#pragma unroll 8
        for (int kk = 0; kk < 64; kk++) {
            const float* xr = xb + kk * 66;
            ull wp = *(const ull*)(wb + kk * 66);
            ull x0 = *(const ull*)(xr + 0);
            ull x1 = *(const ull*)(xr + 2);
            ull x2 = *(const ull*)(xr + 4);
            ull x3 = *(const ull*)(xr + 6);
            asm("fma.rn.f32x2 %0, %1, %2, %0;" : "+l"(acc0) : "l"(x0), "l"(wp));
            asm("fma.rn.f32x2 %0, %1, %2, %0;" : "+l"(acc1) : "l"(x1), "l"(wp));
            asm("fma.rn.f32x2 %0, %1, %2, %0;" : "+l"(acc2) : "l"(x2), "l"(wp));
            asm("fma.rn.f32x2 %0, %1, %2, %0;" : "+l"(acc3) : "l"(x3), "l"(wp));
        }
    }

    float bv = b[lane];
    float lo, hi;
    ull accs[4] = {acc0, acc1, acc2, acc3};
#pragma unroll
    for (int i = 0; i < 4; i++) {
        asm("mov.b64 {%0, %1}, %2;" : "=f"(lo), "=f"(hi) : "l"(accs[i]));
        int r0 = row0 + warp * 8 + 2 * i;
        if (r0 < N_NODES)     g_h[(size_t)r0 * 32 + lane]       = lo + bv;
        if (r0 + 1 < N_NODES) g_h[(size_t)(r0 + 1) * 32 + lane] = hi + bv;
    }
}

// ---------------- propagation step (pull, warp per node, lane = out dim) ----------------
__global__ __launch_bounds__(256) void k_prop(int srcSel, int dstSel, float* __restrict__ dout) {
    int gw   = (blockIdx.x * blockDim.x + threadIdx.x) >> 5;
    int lane = threadIdx.x & 31;
    const float* zin = (srcSel == 0) ? g_h : (srcSel == 1) ? g_z : dout;
    float* zout = (dstSel == 1) ? g_z : dout;

    int start = g_rowptr[gw];
    int end   = g_rowptr[gw + 1];

    float acc = 0.f, accB = 0.f;
    for (int base = start; base < end; base += 32) {
        int m = end - base;
        if (m > 32) m = 32;
        float2 p = make_float2(0.f, 0.f);
        if (lane < m) p = g_packed[base + lane];
        int   si = __float_as_int(p.x);
        float wi = p.y;
        int kk = 0;
        for (; kk + 4 <= m; kk += 4) {
            int s0 = __shfl_sync(0xffffffffu, si, kk);
            int s1 = __shfl_sync(0xffffffffu, si, kk + 1);
            int s2 = __shfl_sync(0xffffffffu, si, kk + 2);
            int s3 = __shfl_sync(0xffffffffu, si, kk + 3);
            float w0 = __shfl_sync(0xffffffffu, wi, kk);
            float w1 = __shfl_sync(0xffffffffu, wi, kk + 1);
            float w2 = __shfl_sync(0xffffffffu, wi, kk + 2);
            float w3 = __shfl_sync(0xffffffffu, wi, kk + 3);
            float z0 = zin[s0 * 32 + lane];
            float z1 = zin[s1 * 32 + lane];
            float z2 = zin[s2 * 32 + lane];
            float z3 = zin[s3 * 32 + lane];
            acc  = fmaf(w0, z0, acc);
            accB = fmaf(w1, z1, accB);
            acc  = fmaf(w2, z2, acc);
            accB = fmaf(w3, z3, accB);
        }
        for (; kk < m; kk++) {
            int   s = __shfl_sync(0xffffffffu, si, kk);
            float w = __shfl_sync(0xffffffffu, wi, kk);
            acc = fmaf(w, zin[s * 32 + lane], acc);
        }
    }
    float di = g_dinv[gw];
    float zi = zin[gw * 32 + lane];
    float agg = di * fmaf(di, zi, acc + accB);
    zout[gw * 32 + lane] = (1.0f - ALPHA) * agg + ALPHA * g_h[gw * 32 + lane];
}

// ---------------- host launcher ----------------
extern "C" void kernel_launch(void* const* d_in, const int* in_sizes, int n_in,
                              void* d_out, int out_size) {
    const float* x  = (const float*)d_in[0];
    const float* W  = (const float*)d_in[1];
    const float* b  = (const float*)d_in[2];
    const void*  ei = d_in[3];
    float* out = (float*)d_out;

    const int NB = (N_NODES + 1023) / 1024;   // 98

    k_detect<<<1, 1>>>((const int*)ei);
    k_init_deg<<<(N_NODES + 255) / 256, 256>>>();
    k_decode_count<<<(N_EDGES + 255) / 256, 256>>>(ei);
    k_dinv<<<(N_NODES + 255) / 256, 256>>>();
    k_blocksum<<<NB, 256>>>();
    k_scanpartial<<<1, 32>>>(NB);
    k_blockscan<<<NB, 256>>>();
    k_scatter<<<N_EDGES / 256, 256>>>();
    k_gemm<<<(N_NODES + 63) / 64, 256>>>(x, W, b);

    // step 1 reads h, writes g_z; even steps write dout; odd steps (>=3) write g_z.
    k_prop<<<N_NODES * 32 / 256, 256>>>(0, 1, out);
    for (int s = 2; s <= KSTEPS; s++) {
        if ((s & 1) == 0) k_prop<<<N_NODES * 32 / 256, 256>>>(1, 2, out);
        else              k_prop<<<N_NODES * 32 / 256, 256>>>(2, 1, out);
    }
}

// round 7
// speedup vs baseline: 1.3483x; 1.0445x over previous
#include <cuda_runtime.h>
#include <cuda_bf16.h>

#define N_NODES 100000
#define N_EDGES 1600000
#define IN_DIM  512
#define OUT_DIM 32
#define KSTEPS  10
#define ALPHA   0.1f

typedef unsigned long long ull;

// ---------------- device scratch (allocation-free) ----------------
__device__ float  g_h[N_NODES * OUT_DIM];      // 12.8 MB  (projection)
__device__ float  g_z[N_NODES * OUT_DIM];      // 12.8 MB  scaled-z ping
__device__ float  g_z2[N_NODES * OUT_DIM];     // 12.8 MB  scaled-z pong
__device__ int    g_src[N_EDGES];
__device__ int    g_dst[N_EDGES];
__device__ int    g_deg[N_NODES];
__device__ float  g_dinv[N_NODES];
__device__ int    g_rowptr[N_NODES + 1];
__device__ int    g_cursor[N_NODES];
__device__ int    g_pidx[N_EDGES];             // CSR col index (src), 4B/edge
__device__ int    g_partial[128];
__device__ int    g_is64;

// ---------------- init degrees + dtype sniff (fused) ----------------
__global__ void k_init_detect(const int* __restrict__ e32) {
    int i = blockIdx.x * blockDim.x + threadIdx.x;
    if (i < N_NODES) g_deg[i] = 1;   // self loop
    if (i == 0) {
        int ok = 1;
#pragma unroll
        for (int q = 1; q < 64; q += 2)
            if (e32[q] != 0) ok = 0;
        g_is64 = ok;
    }
}

// ---------------- decode edges + count in-degrees (fused) ----------------
__global__ void k_decode_count(const void* __restrict__ ei) {
    int e = blockIdx.x * blockDim.x + threadIdx.x;
    if (e >= N_EDGES) return;
    int s, d;
    if (g_is64) {
        const long long* p = (const long long*)ei;
        s = (int)p[e];
        d = (int)p[N_EDGES + e];
    } else {
        const int* p = (const int*)ei;
        s = p[e];
        d = p[N_EDGES + e];
    }
    if (s < 0) s = 0; if (s >= N_NODES) s = N_NODES - 1;
    if (d < 0) d = 0; if (d >= N_NODES) d = N_NODES - 1;
    g_src[e] = s;
    g_dst[e] = d;
    atomicAdd(&g_deg[d], 1);
}

// ---------------- dinv = rsqrt(deg) + per-block sums of (deg-1) (fused) ----------------
__global__ void k_dinv_blocksum() {
    int base = blockIdx.x * 1024;
    int t = threadIdx.x;
    int s = 0;
#pragma unroll
    for (int i = 0; i < 4; i++) {
        int idx = base + t * 4 + i;
        if (idx < N_NODES) {
            int d = g_deg[idx];
            g_dinv[idx] = rsqrtf((float)d);
            s += d - 1;
        }
    }
#pragma unroll
    for (int o = 16; o; o >>= 1) s += __shfl_down_sync(0xffffffffu, s, o);
    __shared__ int ws[8];
    if ((t & 31) == 0) ws[t >> 5] = s;
    __syncthreads();
    if (t == 0) {
        int tot = 0;
#pragma unroll
        for (int i = 0; i < 8; i++) tot += ws[i];
        g_partial[blockIdx.x] = tot;
    }
}

// ---------------- exclusive scan of block sums (1 warp) ----------------
__global__ void k_scanpartial(int nb) {
    int lane = threadIdx.x;
    int v[4];
    int tsum = 0;
#pragma unroll
    for (int i = 0; i < 4; i++) {
        int idx = lane * 4 + i;
        v[i] = (idx < nb) ? g_partial[idx] : 0;
        tsum += v[i];
    }
    int inc = tsum;
#pragma unroll
    for (int o = 1; o < 32; o <<= 1) {
        int y = __shfl_up_sync(0xffffffffu, inc, o);
        if (lane >= o) inc += y;
    }
    int run = inc - tsum;   // exclusive
#pragma unroll
    for (int i = 0; i < 4; i++) {
        int idx = lane * 4 + i;
        if (idx < nb) { g_partial[idx] = run; run += v[i]; }
    }
    int total = __shfl_sync(0xffffffffu, inc, 31);
    if (lane == 0) g_rowptr[N_NODES] = total;
}

// ---------------- full exclusive scan -> rowptr & cursor ----------------
__global__ void k_blockscan() {
    int t = threadIdx.x;
    int base = blockIdx.x * 1024 + t * 4;
    int v[4];
    int tsum = 0;
#pragma unroll
    for (int i = 0; i < 4; i++) {
        int idx = base + i;
        v[i] = (idx < N_NODES) ? (g_deg[idx] - 1) : 0;
        tsum += v[i];
    }
    int lane = t & 31, warp = t >> 5;
    int inc = tsum;
#pragma unroll
    for (int o = 1; o < 32; o <<= 1) {
        int y = __shfl_up_sync(0xffffffffu, inc, o);
        if (lane >= o) inc += y;
    }
    int excl = inc - tsum;
    __shared__ int wtot[8];
    if (lane == 31) wtot[warp] = inc;
    __syncthreads();
    if (t == 0) {
        int acc = 0;
#pragma unroll
        for (int i = 0; i < 8; i++) { int x = wtot[i]; wtot[i] = acc; acc += x; }
    }
    __syncthreads();
    int off = g_partial[blockIdx.x] + wtot[warp] + excl;
#pragma unroll
    for (int i = 0; i < 4; i++) {
        int idx = base + i;
        if (idx < N_NODES) { g_rowptr[idx] = off; g_cursor[idx] = off; off += v[i]; }
    }
}

// ---------------- dense projection: h = x @ W^T + b ; zs0 = dinv * h ----------------
// 256 threads (8 warps). Block tile: 64 rows x 32 cols. Warp w owns rows
// 8w..8w+7 (4 row-pairs), lane = output col. k chunked by 64.
// All 64-bit FFMA2 operands come straight from LDS.64 (no packing movs).
__global__ __launch_bounds__(256) void k_gemm(const float* __restrict__ x,
                                              const float* __restrict__ W,
                                              const float* __restrict__ b) {
    __shared__ alignas(16) float xPf[64 * 66];   // 16.9 KB
    __shared__ alignas(16) float Wdf[64 * 66];   // 16.9 KB

    int t    = threadIdx.x;
    int lane = t & 31;
    int warp = t >> 5;
    int row0 = blockIdx.x * 64;

    ull acc0 = 0ull, acc1 = 0ull, acc2 = 0ull, acc3 = 0ull;

    for (int chunk = 0; chunk < 8; chunk++) {
        int k0 = chunk * 64;
        __syncthreads();
        // stage W chunk duplicated: Wdf[kk*66 + 2j (+1)] = W[j][k0+kk]
#pragma unroll
        for (int it = 0; it < 8; it++) {
            int gidx = t + it * 256;        // 0..2047
            int j  = gidx >> 6;             // 0..31
            int kk = gidx & 63;             // 0..63
            float wv = W[j * IN_DIM + k0 + kk];
            Wdf[kk * 66 + 2 * j]     = wv;
            Wdf[kk * 66 + 2 * j + 1] = wv;
        }
        // stage x chunk transposed: xPf[kk*66 + row] = x[row0+row][k0+kk]
#pragma unroll
        for (int it = 0; it < 4; it++) {
            int gidx = t + it * 256;        // 0..1023
            int row = gidx & 63;
            int q   = gidx >> 6;            // 0..15
            int gr  = row0 + row;
            if (gr >= N_NODES) gr = N_NODES - 1;
            float4 xv = *(const float4*)&x[(size_t)gr * IN_DIM + k0 + q * 4];
            xPf[(q * 4 + 0) * 66 + row] = xv.x;
            xPf[(q * 4 + 1) * 66 + row] = xv.y;
            xPf[(q * 4 + 2) * 66 + row] = xv.z;
            xPf[(q * 4 + 3) * 66 + row] = xv.w;
        }
        __syncthreads();

        const float* xb = &xPf[warp * 8];
        const float* wb = &Wdf[2 * lane];
#pragma unroll 8
        for (int kk = 0; kk < 64; kk++) {
            const float* xr = xb + kk * 66;
            ull wp = *(const ull*)(wb + kk * 66);
            ull x0 = *(const ull*)(xr + 0);
            ull x1 = *(const ull*)(xr + 2);
            ull x2 = *(const ull*)(xr + 4);
            ull x3 = *(const ull*)(xr + 6);
            asm("fma.rn.f32x2 %0, %1, %2, %0;" : "+l"(acc0) : "l"(x0), "l"(wp));
            asm("fma.rn.f32x2 %0, %1, %2, %0;" : "+l"(acc1) : "l"(x1), "l"(wp));
            asm("fma.rn.f32x2 %0, %1, %2, %0;" : "+l"(acc2) : "l"(x2), "l"(wp));
            asm("fma.rn.f32x2 %0, %1, %2, %0;" : "+l"(acc3) : "l"(x3), "l"(wp));
        }
    }

    float bv = b[lane];
    float lo, hi;
    ull accs[4] = {acc0, acc1, acc2, acc3};
#pragma unroll
    for (int i = 0; i < 4; i++) {
        asm("mov.b64 {%0, %1}, %2;" : "=f"(lo), "=f"(hi) : "l"(accs[i]));
        int r0 = row0 + warp * 8 + 2 * i;
        if (r0 < N_NODES) {
            float v = lo + bv;
            g_h[(size_t)r0 * 32 + lane] = v;
            g_z[(size_t)r0 * 32 + lane] = g_dinv[r0] * v;
        }
        if (r0 + 1 < N_NODES) {
            float v = hi + bv;
            g_h[(size_t)(r0 + 1) * 32 + lane] = v;
            g_z[(size_t)(r0 + 1) * 32 + lane] = g_dinv[r0 + 1] * v;
        }
    }
}

// ---------------- CSR scatter (index only) ----------------
__global__ void k_scatter() {
    int e = blockIdx.x * blockDim.x + threadIdx.x;
    if (e >= N_EDGES) return;
    int s = g_src[e];
    int d = g_dst[e];
    int pos = atomicAdd(&g_cursor[d], 1);
    g_pidx[pos] = s;
}

// ---------------- propagation step (pull, warp per node, prescaled z) ----------------
// zs = dinv * z. agg_i = dinv_i * (sum_{j in N(i)} zs_j + zs_i).
// Steps 1..9 write zs_new = dinv * z_new (ping-pong); step 10 writes z_new to dout.
__global__ __launch_bounds__(256) void k_prop(int srcSel, int finalStep, float* __restrict__ dout) {
    int gw   = (blockIdx.x * blockDim.x + threadIdx.x) >> 5;
    int lane = threadIdx.x & 31;
    const float* zin = (srcSel == 1) ? g_z : g_z2;
    float* zout = finalStep ? dout : ((srcSel == 1) ? g_z2 : g_z);

    int start = g_rowptr[gw];
    int end   = g_rowptr[gw + 1];

    float acc0 = 0.f, acc1 = 0.f, acc2 = 0.f, acc3 = 0.f;
    for (int base = start; base < end; base += 32) {
        int m = end - base;
        if (m > 32) m = 32;
        int si = (lane < m) ? g_pidx[base + lane] : 0;
        int kk = 0;
        for (; kk + 8 <= m; kk += 8) {
            int s0 = __shfl_sync(0xffffffffu, si, kk);
            int s1 = __shfl_sync(0xffffffffu, si, kk + 1);
            int s2 = __shfl_sync(0xffffffffu, si, kk + 2);
            int s3 = __shfl_sync(0xffffffffu, si, kk + 3);
            int s4 = __shfl_sync(0xffffffffu, si, kk + 4);
            int s5 = __shfl_sync(0xffffffffu, si, kk + 5);
            int s6 = __shfl_sync(0xffffffffu, si, kk + 6);
            int s7 = __shfl_sync(0xffffffffu, si, kk + 7);
            float z0 = zin[s0 * 32 + lane];
            float z1 = zin[s1 * 32 + lane];
            float z2 = zin[s2 * 32 + lane];
            float z3 = zin[s3 * 32 + lane];
            float z4 = zin[s4 * 32 + lane];
            float z5 = zin[s5 * 32 + lane];
            float z6 = zin[s6 * 32 + lane];
            float z7 = zin[s7 * 32 + lane];
            acc0 += z0; acc1 += z1; acc2 += z2; acc3 += z3;
            acc0 += z4; acc1 += z5; acc2 += z6; acc3 += z7;
        }
        for (; kk < m; kk++) {
            int s = __shfl_sync(0xffffffffu, si, kk);
            acc0 += zin[s * 32 + lane];
        }
    }
    float di = g_dinv[gw];
    float zs_self = zin[gw * 32 + lane];
    float agg = di * (((acc0 + acc1) + (acc2 + acc3)) + zs_self);
    float zn  = (1.0f - ALPHA) * agg + ALPHA * g_h[gw * 32 + lane];
    zout[gw * 32 + lane] = finalStep ? zn : di * zn;
}

// ---------------- host launcher ----------------
extern "C" void kernel_launch(void* const* d_in, const int* in_sizes, int n_in,
                              void* d_out, int out_size) {
    const float* x  = (const float*)d_in[0];
    const float* W  = (const float*)d_in[1];
    const float* b  = (const float*)d_in[2];
    const void*  ei = d_in[3];
    float* out = (float*)d_out;

    const int NB = (N_NODES + 1023) / 1024;   // 98

    k_init_detect<<<(N_NODES + 255) / 256, 256>>>((const int*)ei);   // 1
    k_decode_count<<<(N_EDGES + 255) / 256, 256>>>(ei);              // 2
    k_dinv_blocksum<<<NB, 256>>>();                                  // 3
    k_scanpartial<<<1, 32>>>(NB);                                    // 4
    k_blockscan<<<NB, 256>>>();                                      // 5
    k_gemm<<<(N_NODES + 63) / 64, 256>>>(x, W, b);                   // 6 (profiled)
    k_scatter<<<N_EDGES / 256, 256>>>();                             // 7

    // 10 steps: zs ping-pongs g_z (srcSel=1) <-> g_z2 (srcSel=2); final writes dout.
    int srcSel = 1;
    for (int s = 1; s <= KSTEPS; s++) {
        k_prop<<<N_NODES * 32 / 256, 256>>>(srcSel, (s == KSTEPS) ? 1 : 0, out);
        srcSel = 3 - srcSel;
    }
}

// round 8
// speedup vs baseline: 1.4551x; 1.0792x over previous
#include <cuda_runtime.h>
#include <cuda_bf16.h>

#define N_NODES 100000
#define N_EDGES 1600000
#define IN_DIM  512
#define OUT_DIM 32
#define KSTEPS  10
#define ALPHA   0.1f

typedef unsigned long long ull;

// ---------------- device scratch (allocation-free) ----------------
__device__ float  g_h[N_NODES * OUT_DIM];      // 12.8 MB  (projection)
__device__ float  g_z[N_NODES * OUT_DIM];      // 12.8 MB  scaled-z ping
__device__ float  g_z2[N_NODES * OUT_DIM];     // 12.8 MB  scaled-z pong
__device__ int    g_src[N_EDGES];
__device__ int    g_dst[N_EDGES];
__device__ int    g_deg[N_NODES];
__device__ float  g_dinv[N_NODES];
__device__ int    g_rowptr[N_NODES + 1];
__device__ int    g_cursor[N_NODES];
__device__ int    g_pidx[N_EDGES];             // CSR col index (src), 4B/edge
__device__ int    g_partial[128];
__device__ int    g_is64;

// ---------------- init degrees + dtype sniff (fused) ----------------
__global__ void k_init_detect(const int* __restrict__ e32) {
    int i = blockIdx.x * blockDim.x + threadIdx.x;
    if (i < N_NODES) g_deg[i] = 1;   // self loop
    if (i == 0) {
        int ok = 1;
#pragma unroll
        for (int q = 1; q < 64; q += 2)
            if (e32[q] != 0) ok = 0;
        g_is64 = ok;
    }
}

// ---------------- decode edges + count in-degrees (fused) ----------------
__global__ void k_decode_count(const void* __restrict__ ei) {
    int e = blockIdx.x * blockDim.x + threadIdx.x;
    if (e >= N_EDGES) return;
    int s, d;
    if (g_is64) {
        const long long* p = (const long long*)ei;
        s = (int)p[e];
        d = (int)p[N_EDGES + e];
    } else {
        const int* p = (const int*)ei;
        s = p[e];
        d = p[N_EDGES + e];
    }
    if (s < 0) s = 0; if (s >= N_NODES) s = N_NODES - 1;
    if (d < 0) d = 0; if (d >= N_NODES) d = N_NODES - 1;
    g_src[e] = s;
    g_dst[e] = d;
    atomicAdd(&g_deg[d], 1);
}

// ---------------- dinv = rsqrt(deg) + per-block sums of (deg-1) (fused) ----------------
__global__ void k_dinv_blocksum() {
    int base = blockIdx.x * 1024;
    int t = threadIdx.x;
    int s = 0;
#pragma unroll
    for (int i = 0; i < 4; i++) {
        int idx = base + t * 4 + i;
        if (idx < N_NODES) {
            int d = g_deg[idx];
            g_dinv[idx] = rsqrtf((float)d);
            s += d - 1;
        }
    }
#pragma unroll
    for (int o = 16; o; o >>= 1) s += __shfl_down_sync(0xffffffffu, s, o);
    __shared__ int ws[8];
    if ((t & 31) == 0) ws[t >> 5] = s;
    __syncthreads();
    if (t == 0) {
        int tot = 0;
#pragma unroll
        for (int i = 0; i < 8; i++) tot += ws[i];
        g_partial[blockIdx.x] = tot;
    }
}

// ---------------- exclusive scan of block sums (1 warp) ----------------
__global__ void k_scanpartial(int nb) {
    int lane = threadIdx.x;
    int v[4];
    int tsum = 0;
#pragma unroll
    for (int i = 0; i < 4; i++) {
        int idx = lane * 4 + i;
        v[i] = (idx < nb) ? g_partial[idx] : 0;
        tsum += v[i];
    }
    int inc = tsum;
#pragma unroll
    for (int o = 1; o < 32; o <<= 1) {
        int y = __shfl_up_sync(0xffffffffu, inc, o);
        if (lane >= o) inc += y;
    }
    int run = inc - tsum;   // exclusive
#pragma unroll
    for (int i = 0; i < 4; i++) {
        int idx = lane * 4 + i;
        if (idx < nb) { g_partial[idx] = run; run += v[i]; }
    }
    int total = __shfl_sync(0xffffffffu, inc, 31);
    if (lane == 0) g_rowptr[N_NODES] = total;
}

// ---------------- full exclusive scan -> rowptr & cursor ----------------
__global__ void k_blockscan() {
    int t = threadIdx.x;
    int base = blockIdx.x * 1024 + t * 4;
    int v[4];
    int tsum = 0;
#pragma unroll
    for (int i = 0; i < 4; i++) {
        int idx = base + i;
        v[i] = (idx < N_NODES) ? (g_deg[idx] - 1) : 0;
        tsum += v[i];
    }
    int lane = t & 31, warp = t >> 5;
    int inc = tsum;
#pragma unroll
    for (int o = 1; o < 32; o <<= 1) {
        int y = __shfl_up_sync(0xffffffffu, inc, o);
        if (lane >= o) inc += y;
    }
    int excl = inc - tsum;
    __shared__ int wtot[8];
    if (lane == 31) wtot[warp] = inc;
    __syncthreads();
    if (t == 0) {
        int acc = 0;
#pragma unroll
        for (int i = 0; i < 8; i++) { int x = wtot[i]; wtot[i] = acc; acc += x; }
    }
    __syncthreads();
    int off = g_partial[blockIdx.x] + wtot[warp] + excl;
#pragma unroll
    for (int i = 0; i < 4; i++) {
        int idx = base + i;
        if (idx < N_NODES) { g_rowptr[idx] = off; g_cursor[idx] = off; off += v[i]; }
    }
}

// ---------------- dense projection: h = x @ W^T + b ; zs0 = dinv * h ----------------
__global__ __launch_bounds__(256) void k_gemm(const float* __restrict__ x,
                                              const float* __restrict__ W,
                                              const float* __restrict__ b) {
    __shared__ alignas(16) float xPf[64 * 66];   // 16.9 KB
    __shared__ alignas(16) float Wdf[64 * 66];   // 16.9 KB

    int t    = threadIdx.x;
    int lane = t & 31;
    int warp = t >> 5;
    int row0 = blockIdx.x * 64;

    ull acc0 = 0ull, acc1 = 0ull, acc2 = 0ull, acc3 = 0ull;

    for (int chunk = 0; chunk < 8; chunk++) {
        int k0 = chunk * 64;
        __syncthreads();
        // stage W chunk duplicated: Wdf[kk*66 + 2j (+1)] = W[j][k0+kk]
#pragma unroll
        for (int it = 0; it < 8; it++) {
            int gidx = t + it * 256;        // 0..2047
            int j  = gidx >> 6;             // 0..31
            int kk = gidx & 63;             // 0..63
            float wv = W[j * IN_DIM + k0 + kk];
            Wdf[kk * 66 + 2 * j]     = wv;
            Wdf[kk * 66 + 2 * j + 1] = wv;
        }
        // stage x chunk transposed: xPf[kk*66 + row] = x[row0+row][k0+kk]
#pragma unroll
        for (int it = 0; it < 4; it++) {
            int gidx = t + it * 256;        // 0..1023
            int row = gidx & 63;
            int q   = gidx >> 6;            // 0..15
            int gr  = row0 + row;
            if (gr >= N_NODES) gr = N_NODES - 1;
            float4 xv = *(const float4*)&x[(size_t)gr * IN_DIM + k0 + q * 4];
            xPf[(q * 4 + 0) * 66 + row] = xv.x;
            xPf[(q * 4 + 1) * 66 + row] = xv.y;
            xPf[(q * 4 + 2) * 66 + row] = xv.z;
            xPf[(q * 4 + 3) * 66 + row] = xv.w;
        }
        __syncthreads();

        const float* xb = &xPf[warp * 8];
        const float* wb = &Wdf[2 * lane];
#pragma unroll 8
        for (int kk = 0; kk < 64; kk++) {
            const float* xr = xb + kk * 66;
            ull wp = *(const ull*)(wb + kk * 66);
            ull x0 = *(const ull*)(xr + 0);
            ull x1 = *(const ull*)(xr + 2);
            ull x2 = *(const ull*)(xr + 4);
            ull x3 = *(const ull*)(xr + 6);
            asm("fma.rn.f32x2 %0, %1, %2, %0;" : "+l"(acc0) : "l"(x0), "l"(wp));
            asm("fma.rn.f32x2 %0, %1, %2, %0;" : "+l"(acc1) : "l"(x1), "l"(wp));
            asm("fma.rn.f32x2 %0, %1, %2, %0;" : "+l"(acc2) : "l"(x2), "l"(wp));
            asm("fma.rn.f32x2 %0, %1, %2, %0;" : "+l"(acc3) : "l"(x3), "l"(wp));
        }
    }

    float bv = b[lane];
    float lo, hi;
    ull accs[4] = {acc0, acc1, acc2, acc3};
#pragma unroll
    for (int i = 0; i < 4; i++) {
        asm("mov.b64 {%0, %1}, %2;" : "=f"(lo), "=f"(hi) : "l"(accs[i]));
        int r0 = row0 + warp * 8 + 2 * i;
        if (r0 < N_NODES) {
            float v = lo + bv;
            g_h[(size_t)r0 * 32 + lane] = v;
            g_z[(size_t)r0 * 32 + lane] = g_dinv[r0] * v;
        }
        if (r0 + 1 < N_NODES) {
            float v = hi + bv;
            g_h[(size_t)(r0 + 1) * 32 + lane] = v;
            g_z[(size_t)(r0 + 1) * 32 + lane] = g_dinv[r0 + 1] * v;
        }
    }
}

// ---------------- CSR scatter (index only) ----------------
__global__ void k_scatter() {
    int e = blockIdx.x * blockDim.x + threadIdx.x;
    if (e >= N_EDGES) return;
    int s = g_src[e];
    int d = g_dst[e];
    int pos = atomicAdd(&g_cursor[d], 1);
    g_pidx[pos] = s;
}

// ---------------- propagation step (pull, warp per node, paired float2 gathers) ----
// zs = dinv*z, all edge weights 1. Lanes 0-15 gather row A (float2/lane),
// lanes 16-31 gather row B in the SAME LDG.64 -> 2 rows per load instruction.
// Half-warp partials combined via shfl_xor(16) at the end.
__global__ __launch_bounds__(256) void k_prop(int srcSel, int finalStep, float* __restrict__ dout) {
    int gw   = (blockIdx.x * blockDim.x + threadIdx.x) >> 5;
    int lane = threadIdx.x & 31;
    int half = lane >> 4;     // 0: row A, 1: row B
    int hl   = lane & 15;     // float2 slot within row
    const float2* zin2 = (const float2*)((srcSel == 1) ? g_z : g_z2);
    float* zoutf = finalStep ? dout : ((srcSel == 1) ? (float*)g_z2 : (float*)g_z);

    int start = g_rowptr[gw];
    int end   = g_rowptr[gw + 1];

    float ax = 0.f, ay = 0.f, bx = 0.f, by = 0.f;
    for (int base = start; base < end; base += 32) {
        int m = end - base;
        if (m > 32) m = 32;
        int si = (lane < m) ? g_pidx[base + lane] : 0;
        int kk = 0;
        for (; kk + 16 <= m; kk += 16) {
            int s[8];
#pragma unroll
            for (int p = 0; p < 8; p++)
                s[p] = __shfl_sync(0xffffffffu, si, kk + 2 * p + half);
            float2 v[8];
#pragma unroll
            for (int p = 0; p < 8; p++)
                v[p] = zin2[(size_t)s[p] * 16 + hl];
#pragma unroll
            for (int p = 0; p < 8; p += 2) {
                ax += v[p].x;     ay += v[p].y;
                bx += v[p + 1].x; by += v[p + 1].y;
            }
        }
        for (; kk < m; kk += 2) {
            int idx2 = kk + half;
            int srcl = (idx2 < m) ? idx2 : kk;
            int s = __shfl_sync(0xffffffffu, si, srcl);
            float2 v = zin2[(size_t)s * 16 + hl];
            if (idx2 < m) { ax += v.x; ay += v.y; }
        }
    }
    // combine the two half-warp accumulators
    float sx = ax + bx, sy = ay + by;
    sx += __shfl_xor_sync(0xffffffffu, sx, 16);
    sy += __shfl_xor_sync(0xffffffffu, sy, 16);

    float di = g_dinv[gw];
    float2 zself = zin2[(size_t)gw * 16 + hl];
    float2 hv    = ((const float2*)g_h)[(size_t)gw * 16 + hl];
    float znx = (1.0f - ALPHA) * (di * (sx + zself.x)) + ALPHA * hv.x;
    float zny = (1.0f - ALPHA) * (di * (sy + zself.y)) + ALPHA * hv.y;
    if (!finalStep) { znx *= di; zny *= di; }
    if (half == 0)
        *(float2*)&zoutf[(size_t)gw * 32 + 2 * hl] = make_float2(znx, zny);
}

// ---------------- host launcher ----------------
extern "C" void kernel_launch(void* const* d_in, const int* in_sizes, int n_in,
                              void* d_out, int out_size) {
    const float* x  = (const float*)d_in[0];
    const float* W  = (const float*)d_in[1];
    const float* b  = (const float*)d_in[2];
    const void*  ei = d_in[3];
    float* out = (float*)d_out;

    const int NB = (N_NODES + 1023) / 1024;   // 98

    k_init_detect<<<(N_NODES + 255) / 256, 256>>>((const int*)ei);   // 1
    k_decode_count<<<(N_EDGES + 255) / 256, 256>>>(ei);              // 2
    k_dinv_blocksum<<<NB, 256>>>();                                  // 3
    k_gemm<<<(N_NODES + 63) / 64, 256>>>(x, W, b);                   // 4 (ncu window)
    k_scanpartial<<<1, 32>>>(NB);                                    // 5
    k_blockscan<<<NB, 256>>>();                                      // 6
    k_scatter<<<N_EDGES / 256, 256>>>();                             // 7

    // 10 steps: zs ping-pongs g_z (srcSel=1) <-> g_z2 (srcSel=2); final writes dout.
    int srcSel = 1;
    for (int s = 1; s <= KSTEPS; s++) {
        k_prop<<<N_NODES * 32 / 256, 256>>>(srcSel, (s == KSTEPS) ? 1 : 0, out);
        srcSel = 3 - srcSel;
    }
}

// round 9
// speedup vs baseline: 1.5276x; 1.0498x over previous
#include <cuda_runtime.h>
#include <cuda_bf16.h>

#define N_NODES 100000
#define N_EDGES 1600000
#define IN_DIM  512
#define OUT_DIM 32
#define KSTEPS  10
#define ALPHA   0.1f

typedef unsigned long long ull;

// ---------------- device scratch (allocation-free) ----------------
__device__ float  g_h[N_NODES * OUT_DIM];      // 12.8 MB  (projection)
__device__ float  g_z[N_NODES * OUT_DIM];      // 12.8 MB  scaled-z ping
__device__ float  g_z2[N_NODES * OUT_DIM];     // 12.8 MB  scaled-z pong
__device__ int    g_src[N_EDGES];
__device__ int    g_dst[N_EDGES];
__device__ int    g_deg[N_NODES];
__device__ float  g_dinv[N_NODES];
__device__ int    g_rowptr[N_NODES + 1];
__device__ int    g_cursor[N_NODES];
__device__ int    g_pidx[N_EDGES];             // CSR col index (src), 4B/edge
__device__ int    g_partial[128];
__device__ int    g_is64;

// ---------------- init degrees + dtype sniff (fused) ----------------
__global__ void k_init_detect(const int* __restrict__ e32) {
    int i = blockIdx.x * blockDim.x + threadIdx.x;
    if (i < N_NODES) g_deg[i] = 1;   // self loop
    if (i == 0) {
        int ok = 1;
#pragma unroll
        for (int q = 1; q < 64; q += 2)
            if (e32[q] != 0) ok = 0;
        g_is64 = ok;
    }
}

// ---------------- decode edges + count in-degrees (fused) ----------------
__global__ void k_decode_count(const void* __restrict__ ei) {
    int e = blockIdx.x * blockDim.x + threadIdx.x;
    if (e >= N_EDGES) return;
    int s, d;
    if (g_is64) {
        const long long* p = (const long long*)ei;
        s = (int)p[e];
        d = (int)p[N_EDGES + e];
    } else {
        const int* p = (const int*)ei;
        s = p[e];
        d = p[N_EDGES + e];
    }
    if (s < 0) s = 0; if (s >= N_NODES) s = N_NODES - 1;
    if (d < 0) d = 0; if (d >= N_NODES) d = N_NODES - 1;
    g_src[e] = s;
    g_dst[e] = d;
    atomicAdd(&g_deg[d], 1);
}

// ---------------- dinv = rsqrt(deg) + per-block sums of (deg-1) (fused) ----------------
__global__ void k_dinv_blocksum() {
    int base = blockIdx.x * 1024;
    int t = threadIdx.x;
    int s = 0;
#pragma unroll
    for (int i = 0; i < 4; i++) {
        int idx = base + t * 4 + i;
        if (idx < N_NODES) {
            int d = g_deg[idx];
            g_dinv[idx] = rsqrtf((float)d);
            s += d - 1;
        }
    }
#pragma unroll
    for (int o = 16; o; o >>= 1) s += __shfl_down_sync(0xffffffffu, s, o);
    __shared__ int ws[8];
    if ((t & 31) == 0) ws[t >> 5] = s;
    __syncthreads();
    if (t == 0) {
        int tot = 0;
#pragma unroll
        for (int i = 0; i < 8; i++) tot += ws[i];
        g_partial[blockIdx.x] = tot;
    }
}

// ---------------- exclusive scan of block sums (1 warp) ----------------
__global__ void k_scanpartial(int nb) {
    int lane = threadIdx.x;
    int v[4];
    int tsum = 0;
#pragma unroll
    for (int i = 0; i < 4; i++) {
        int idx = lane * 4 + i;
        v[i] = (idx < nb) ? g_partial[idx] : 0;
        tsum += v[i];
    }
    int inc = tsum;
#pragma unroll
    for (int o = 1; o < 32; o <<= 1) {
        int y = __shfl_up_sync(0xffffffffu, inc, o);
        if (lane >= o) inc += y;
    }
    int run = inc - tsum;   // exclusive
#pragma unroll
    for (int i = 0; i < 4; i++) {
        int idx = lane * 4 + i;
        if (idx < nb) { g_partial[idx] = run; run += v[i]; }
    }
    int total = __shfl_sync(0xffffffffu, inc, 31);
    if (lane == 0) g_rowptr[N_NODES] = total;
}

// ---------------- full exclusive scan -> rowptr & cursor ----------------
__global__ void k_blockscan() {
    int t = threadIdx.x;
    int base = blockIdx.x * 1024 + t * 4;
    int v[4];
    int tsum = 0;
#pragma unroll
    for (int i = 0; i < 4; i++) {
        int idx = base + i;
        v[i] = (idx < N_NODES) ? (g_deg[idx] - 1) : 0;
        tsum += v[i];
    }
    int lane = t & 31, warp = t >> 5;
    int inc = tsum;
#pragma unroll
    for (int o = 1; o < 32; o <<= 1) {
        int y = __shfl_up_sync(0xffffffffu, inc, o);
        if (lane >= o) inc += y;
    }
    int excl = inc - tsum;
    __shared__ int wtot[8];
    if (lane == 31) wtot[warp] = inc;
    __syncthreads();
    if (t == 0) {
        int acc = 0;
#pragma unroll
        for (int i = 0; i < 8; i++) { int x = wtot[i]; wtot[i] = acc; acc += x; }
    }
    __syncthreads();
    int off = g_partial[blockIdx.x] + wtot[warp] + excl;
#pragma unroll
    for (int i = 0; i < 4; i++) {
        int idx = base + i;
        if (idx < N_NODES) { g_rowptr[idx] = off; g_cursor[idx] = off; off += v[i]; }
    }
}

// ---------------- dense projection: h = x @ W^T + b ; zs0 = dinv * h ----------------
// Block 256 thr = 8 warps, tile 128 rows x 32 cols; warp = 16 rows x 32 cols;
// thread = 4 rows x 4 cols. k chunked by 16.
//   xdup[kk][2r],[2r+1] = x[row0+r][k0+kk]  -> LDS.128 = two (x,x) f32x2 operands
//   WT[kk][j]           = W[j][k0+kk]       -> LDS.128 = two (Wc,Wc+1) pairs
// Per lane per kk: 3 LDS.128 + 8 FFMA2 (warp: 3 smem wavefronts per 8 FFMA2).
__global__ __launch_bounds__(256) void k_gemm(const float* __restrict__ x,
                                              const float* __restrict__ W,
                                              const float* __restrict__ b) {
    __shared__ alignas(16) float xdup[16][264];   // 16.9 KB
    __shared__ alignas(16) float WT[16][36];      //  2.3 KB

    int t    = threadIdx.x;
    int lane = t & 31;
    int warp = t >> 5;
    int rg   = lane >> 3;      // row group 0..3
    int cg   = lane & 7;       // col group 0..7
    int row0 = blockIdx.x * 128;

    ull acc[4][2];
#pragma unroll
    for (int i = 0; i < 4; i++) { acc[i][0] = 0ull; acc[i][1] = 0ull; }

    const float* xb = &xdup[0][0] + warp * 32 + rg * 8;   // 2*(16w+4rg)
    const float* wb = &WT[0][0] + 4 * cg;

    for (int chunk = 0; chunk < 32; chunk++) {
        int k0 = chunk * 16;
        __syncthreads();
        // stage WT: 32 cols x 16 kk
#pragma unroll
        for (int it = 0; it < 2; it++) {
            int idx = t + it * 256;      // 0..511
            int j  = idx >> 4;           // 0..31
            int kk = idx & 15;
            WT[kk][j] = W[j * IN_DIM + k0 + kk];
        }
        // stage xdup: 128 rows x 16 kk, duplicated pairs
#pragma unroll
        for (int it = 0; it < 2; it++) {
            int idx = t + it * 256;      // 0..511
            int row = idx >> 2;          // 0..127
            int q   = idx & 3;           // float4 within k-chunk
            int gr  = row0 + row;
            if (gr >= N_NODES) gr = N_NODES - 1;
            float4 xv = *(const float4*)&x[(size_t)gr * IN_DIM + k0 + q * 4];
            int c = 2 * row;
            *(float2*)&xdup[q * 4 + 0][c] = make_float2(xv.x, xv.x);
            *(float2*)&xdup[q * 4 + 1][c] = make_float2(xv.y, xv.y);
            *(float2*)&xdup[q * 4 + 2][c] = make_float2(xv.z, xv.z);
            *(float2*)&xdup[q * 4 + 3][c] = make_float2(xv.w, xv.w);
        }
        __syncthreads();

#pragma unroll
        for (int kk = 0; kk < 16; kk++) {
            const float* xr = xb + kk * 264;
            const float* wr = wb + kk * 36;
            ulonglong2 xa = *(const ulonglong2*)(xr);       // (r0r0, r1r1)
            ulonglong2 xc = *(const ulonglong2*)(xr + 4);   // (r2r2, r3r3)
            ulonglong2 wv = *(const ulonglong2*)(wr);       // (c0c1, c2c3)
            asm("fma.rn.f32x2 %0, %1, %2, %0;" : "+l"(acc[0][0]) : "l"(xa.x), "l"(wv.x));
            asm("fma.rn.f32x2 %0, %1, %2, %0;" : "+l"(acc[0][1]) : "l"(xa.x), "l"(wv.y));
            asm("fma.rn.f32x2 %0, %1, %2, %0;" : "+l"(acc[1][0]) : "l"(xa.y), "l"(wv.x));
            asm("fma.rn.f32x2 %0, %1, %2, %0;" : "+l"(acc[1][1]) : "l"(xa.y), "l"(wv.y));
            asm("fma.rn.f32x2 %0, %1, %2, %0;" : "+l"(acc[2][0]) : "l"(xc.x), "l"(wv.x));
            asm("fma.rn.f32x2 %0, %1, %2, %0;" : "+l"(acc[2][1]) : "l"(xc.x), "l"(wv.y));
            asm("fma.rn.f32x2 %0, %1, %2, %0;" : "+l"(acc[3][0]) : "l"(xc.y), "l"(wv.x));
            asm("fma.rn.f32x2 %0, %1, %2, %0;" : "+l"(acc[3][1]) : "l"(xc.y), "l"(wv.y));
        }
    }

    float4 bv = *(const float4*)&b[4 * cg];
#pragma unroll
    for (int i = 0; i < 4; i++) {
        int r = row0 + warp * 16 + rg * 4 + i;
        if (r < N_NODES) {
            float v0, v1, v2, v3;
            asm("mov.b64 {%0, %1}, %2;" : "=f"(v0), "=f"(v1) : "l"(acc[i][0]));
            asm("mov.b64 {%0, %1}, %2;" : "=f"(v2), "=f"(v3) : "l"(acc[i][1]));
            float4 hv = make_float4(v0 + bv.x, v1 + bv.y, v2 + bv.z, v3 + bv.w);
            *(float4*)&g_h[(size_t)r * 32 + 4 * cg] = hv;
            float di = g_dinv[r];
            *(float4*)&g_z[(size_t)r * 32 + 4 * cg] =
                make_float4(hv.x * di, hv.y * di, hv.z * di, hv.w * di);
        }
    }
}

// ---------------- CSR scatter (index only) ----------------
__global__ void k_scatter() {
    int e = blockIdx.x * blockDim.x + threadIdx.x;
    if (e >= N_EDGES) return;
    int s = g_src[e];
    int d = g_dst[e];
    int pos = atomicAdd(&g_cursor[d], 1);
    g_pidx[pos] = s;
}

// ---------------- propagation step (pull, warp per node, paired float2 gathers) ----
__global__ __launch_bounds__(256) void k_prop(int srcSel, int finalStep, float* __restrict__ dout) {
    int gw   = (blockIdx.x * blockDim.x + threadIdx.x) >> 5;
    int lane = threadIdx.x & 31;
    int half = lane >> 4;     // 0: row A, 1: row B
    int hl   = lane & 15;     // float2 slot within row
    const float2* zin2 = (const float2*)((srcSel == 1) ? g_z : g_z2);
    float* zoutf = finalStep ? dout : ((srcSel == 1) ? (float*)g_z2 : (float*)g_z);

    int start = g_rowptr[gw];
    int end   = g_rowptr[gw + 1];

    float ax = 0.f, ay = 0.f, bx = 0.f, by = 0.f;
    for (int base = start; base < end; base += 32) {
        int m = end - base;
        if (m > 32) m = 32;
        int si = (lane < m) ? g_pidx[base + lane] : 0;
        int kk = 0;
        for (; kk + 16 <= m; kk += 16) {
            int s[8];
#pragma unroll
            for (int p = 0; p < 8; p++)
                s[p] = __shfl_sync(0xffffffffu, si, kk + 2 * p + half);
            float2 v[8];
#pragma unroll
            for (int p = 0; p < 8; p++)
                v[p] = zin2[(size_t)s[p] * 16 + hl];
#pragma unroll
            for (int p = 0; p < 8; p += 2) {
                ax += v[p].x;     ay += v[p].y;
                bx += v[p + 1].x; by += v[p + 1].y;
            }
        }
        for (; kk < m; kk += 2) {
            int idx2 = kk + half;
            int srcl = (idx2 < m) ? idx2 : kk;
            int s = __shfl_sync(0xffffffffu, si, srcl);
            float2 v = zin2[(size_t)s * 16 + hl];
            if (idx2 < m) { ax += v.x; ay += v.y; }
        }
    }
    float sx = ax + bx, sy = ay + by;
    sx += __shfl_xor_sync(0xffffffffu, sx, 16);
    sy += __shfl_xor_sync(0xffffffffu, sy, 16);

    float di = g_dinv[gw];
    float2 zself = zin2[(size_t)gw * 16 + hl];
    float2 hv    = ((const float2*)g_h)[(size_t)gw * 16 + hl];
    float znx = (1.0f - ALPHA) * (di * (sx + zself.x)) + ALPHA * hv.x;
    float zny = (1.0f - ALPHA) * (di * (sy + zself.y)) + ALPHA * hv.y;
    if (!finalStep) { znx *= di; zny *= di; }
    if (half == 0)
        *(float2*)&zoutf[(size_t)gw * 32 + 2 * hl] = make_float2(znx, zny);
}

// ---------------- host launcher ----------------
extern "C" void kernel_launch(void* const* d_in, const int* in_sizes, int n_in,
                              void* d_out, int out_size) {
    const float* x  = (const float*)d_in[0];
    const float* W  = (const float*)d_in[1];
    const float* b  = (const float*)d_in[2];
    const void*  ei = d_in[3];
    float* out = (float*)d_out;

    const int NB = (N_NODES + 1023) / 1024;   // 98

    k_init_detect<<<(N_NODES + 255) / 256, 256>>>((const int*)ei);   // 1
    k_decode_count<<<(N_EDGES + 255) / 256, 256>>>(ei);              // 2
    k_dinv_blocksum<<<NB, 256>>>();                                  // 3
    k_gemm<<<(N_NODES + 127) / 128, 256>>>(x, W, b);                 // 4 (ncu window)
    k_scanpartial<<<1, 32>>>(NB);                                    // 5
    k_blockscan<<<NB, 256>>>();                                      // 6
    k_scatter<<<N_EDGES / 256, 256>>>();                             // 7

    // 10 steps: zs ping-pongs g_z (srcSel=1) <-> g_z2 (srcSel=2); final writes dout.
    int srcSel = 1;
    for (int s = 1; s <= KSTEPS; s++) {
        k_prop<<<N_NODES * 32 / 256, 256>>>(srcSel, (s == KSTEPS) ? 1 : 0, out);
        srcSel = 3 - srcSel;
    }
}